// round 3
// baseline (speedup 1.0000x reference)
#include <cuda_runtime.h>
#include <math.h>

constexpr int kN   = 50000;
constexpr int kE   = 800000;
constexpr int kG   = 512;
constexpr int kD   = 128;
constexpr int kEE  = 64;
constexpr int kL   = 4;
constexpr int kNC  = 10;
constexpr int kSB  = (kN + 1023) / 1024;
constexpr float kBNS = 0.9999950000374997f;  // (1+1e-5)^-0.5

typedef unsigned long long u64;

// ---------------- f32x2 packed helpers -------------------------------------
__device__ __forceinline__ u64 pack2(float lo, float hi) {
    u64 r; asm("mov.b64 %0,{%1,%2};" : "=l"(r) : "f"(lo), "f"(hi)); return r;
}
__device__ __forceinline__ u64 splat2(float v) { return pack2(v, v); }
__device__ __forceinline__ void unpack2(u64 p, float& lo, float& hi) {
    asm("mov.b64 {%0,%1},%2;" : "=f"(lo), "=f"(hi) : "l"(p));
}
__device__ __forceinline__ u64 fma2(u64 a, u64 b, u64 c) {
    u64 r; asm("fma.rn.f32x2 %0,%1,%2,%3;" : "=l"(r) : "l"(a), "l"(b), "l"(c)); return r;
}
__device__ __forceinline__ u64 add2(u64 a, u64 b) {
    u64 r; asm("add.rn.f32x2 %0,%1,%2;" : "=l"(r) : "l"(a), "l"(b)); return r;
}
__device__ __forceinline__ u64 mul2(u64 a, u64 b) {
    u64 r; asm("mul.rn.f32x2 %0,%1,%2;" : "=l"(r) : "l"(a), "l"(b)); return r;
}

// ---------------- scratch ----------------------------------------------------
__device__ float g_x[kN * kD];
__device__ float g_xl[kN * kD];
__device__ float g_xr[kN * kD];
__device__ float g_lraw[kN * 8];
__device__ int   g_deg[kN];
__device__ int   g_cur[kN];
__device__ int   g_scan[kN];
__device__ int   g_bt[kSB];
__device__ int   g_boff[kSB];
__device__ int   g_off[kN + 1];
__device__ int   g_csrc[kE];
__device__ int   g_ceid[kE];
__device__ float g_M[kL * 8 * kD];
__device__ float g_bep[kL * kD];
__device__ float g_gsum[kG * kD];

// ---------------- init -------------------------------------------------------
__global__ void zero_init_kernel() {
    int i = blockIdx.x * blockDim.x + threadIdx.x;
    int stride = gridDim.x * blockDim.x;
    for (int t = i; t < kN; t += stride) { g_deg[t] = 0; g_cur[t] = 0; }
}

__global__ void node_encode(const int* __restrict__ xn, const float* __restrict__ emb) {
    int t = blockIdx.x * blockDim.x + threadIdx.x;
    if (t >= kN * kD) return;
    int n = t >> 7, j = t & 127;
    g_x[t] = emb[xn[n] * kD + j];
}

__global__ void count_deg(const int* __restrict__ src, const int* __restrict__ dst) {
    int e = blockIdx.x * blockDim.x + threadIdx.x;
    if (e >= kE) return;
    int s = src[e], d = dst[e];
    if (s != d) atomicAdd(&g_deg[d], 1);
}

// ---------------- scan deg -> off -------------------------------------------
__global__ void scan1() {
    __shared__ int sh[1024];
    int n = blockIdx.x * 1024 + threadIdx.x;
    int v = (n < kN) ? g_deg[n] : 0;
    sh[threadIdx.x] = v;
    __syncthreads();
    for (int o = 1; o < 1024; o <<= 1) {
        int add = (threadIdx.x >= o) ? sh[threadIdx.x - o] : 0;
        __syncthreads();
        sh[threadIdx.x] += add;
        __syncthreads();
    }
    if (n < kN) g_scan[n] = sh[threadIdx.x];
    if (threadIdx.x == 1023) g_bt[blockIdx.x] = sh[1023];
}
__global__ void scan2() {
    if (threadIdx.x == 0) {
        int run = 0;
        for (int b = 0; b < kSB; b++) { g_boff[b] = run; run += g_bt[b]; }
        g_off[kN] = run;
    }
}
__global__ void scan3() {
    int n = blockIdx.x * blockDim.x + threadIdx.x;
    if (n < kN) g_off[n] = g_scan[n] - g_deg[n] + g_boff[n >> 10];
}

__global__ void scatter_csr(const int* __restrict__ src, const int* __restrict__ dst) {
    int e = blockIdx.x * blockDim.x + threadIdx.x;
    if (e >= kE) return;
    int s = src[e], d = dst[e];
    if (s == d) return;
    int pos = atomicAdd(&g_cur[d], 1);
    int idx = g_off[d] + pos;
    g_csrc[idx] = s;
    g_ceid[idx] = e;
}

// lraw[n] = mean of raw edge attrs over incoming non-self edges (0 if none)
__global__ void lraw_from_csr(const float* __restrict__ eattr) {
    int t = blockIdx.x * blockDim.x + threadIdx.x;
    int n = t >> 3, j = t & 7;
    if (n >= kN) return;
    int beg = g_off[n], end = g_off[n + 1];
    float s = 0.f;
    for (int idx = beg; idx < end; idx++) s += eattr[(size_t)g_ceid[idx] * 8 + j];
    int c = end - beg;
    g_lraw[n * 8 + j] = s / (float)(c > 1 ? c : 1);
}

// ---------------- all layers: M = edge_W @ We, bep = edge_b @ We ------------
__global__ void make_M_all(const float* __restrict__ eW, const float* __restrict__ eb,
                           const float* __restrict__ We) {
    int layer = blockIdx.x;
    int t = threadIdx.x;          // 1024
    int k = t >> 7, j = t & 127;
    const float* w = We + (size_t)layer * kEE * kD;
    float acc = 0.f;
#pragma unroll 8
    for (int u = 0; u < kEE; u++) acc += eW[k * kEE + u] * w[u * kD + j];
    g_M[layer * 8 * kD + k * kD + j] = acc;
    if (t < kD) {
        float b = 0.f;
#pragma unroll 8
        for (int u = 0; u < kEE; u++) b += eb[u] * w[u * kD + t];
        g_bep[layer * kD + t] = b;
    }
}

// ---------------- xl = x@Wl+bl, xr = x@Wr+br (f32x2 packed) -----------------
__global__ void xlr_gemm(const float* __restrict__ Wl, const float* __restrict__ bl,
                         const float* __restrict__ Wr, const float* __restrict__ br,
                         int layer) {
    const float* W = (blockIdx.y == 0 ? Wl : Wr) + layer * kD * kD;
    const float* bias = (blockIdx.y == 0 ? bl : br) + layer * kD;
    float* out = blockIdx.y == 0 ? g_xl : g_xr;

    __shared__ __align__(16) float ws[32 * 128];
    __shared__ float xs[32][33];

    int t = threadIdx.x;     // 256
    int cg = t & 31;
    int ng = t >> 5;
    int n0 = blockIdx.x * 32;

    u64 acc2[4][2] = {};
    for (int kt = 0; kt < kD; kt += 32) {
        for (int r = t; r < 32 * 128; r += 256)
            ws[r] = W[(kt + (r >> 7)) * kD + (r & 127)];
        for (int r = t; r < 32 * 32; r += 256) {
            int n = r >> 5, kk = r & 31;
            int nn = n0 + n;
            xs[n][kk] = (nn < kN) ? g_x[nn * kD + kt + kk] : 0.f;
        }
        __syncthreads();
#pragma unroll
        for (int kk = 0; kk < 32; kk++) {
            ulonglong2 wv = *(const ulonglong2*)&ws[kk * 128 + cg * 4];
#pragma unroll
            for (int m = 0; m < 4; m++) {
                u64 xp = splat2(xs[ng * 4 + m][kk]);
                acc2[m][0] = fma2(xp, wv.x, acc2[m][0]);
                acc2[m][1] = fma2(xp, wv.y, acc2[m][1]);
            }
        }
        __syncthreads();
    }
    float4 bv = *(const float4*)(bias + cg * 4);
#pragma unroll
    for (int m = 0; m < 4; m++) {
        int n = n0 + ng * 4 + m;
        if (n < kN) {
            float a0, a1, a2, a3;
            unpack2(acc2[m][0], a0, a1);
            unpack2(acc2[m][1], a2, a3);
            float4 o = make_float4(a0 + bv.x, a1 + bv.y, a2 + bv.z, a3 + bv.w);
            *(float4*)&out[n * kD + cg * 4] = o;
        }
    }
}

// ---------------- fused GAT layer -------------------------------------------
__global__ __launch_bounds__(256) void fused_gat(
        const float* __restrict__ eattr, const float* __restrict__ att,
        const float* __restrict__ gbias, const float* __restrict__ gam,
        const float* __restrict__ bet, int layer) {
    __shared__ __align__(16) float Ms[8 * kD];
    __shared__ __align__(16) float atts[kD];
    __shared__ __align__(16) float beps[kD];

    int t = threadIdx.x;
    for (int r = t; r < 8 * kD; r += 256) Ms[r] = g_M[layer * 8 * kD + r];
    if (t < kD) { atts[t] = att[layer * kD + t]; beps[t] = g_bep[layer * kD + t]; }
    __syncthreads();

    int d = (blockIdx.x * 256 + t) >> 5;
    if (d >= kN) return;
    int lane = t & 31;
    int j0 = lane * 4;

    float4 attv = *(const float4*)&atts[j0];
    ulonglong2 bepp = *(const ulonglong2*)&beps[j0];
    ulonglong2 xrp = *(const ulonglong2*)&g_xr[d * kD + j0];

    int beg = g_off[d], end = g_off[d + 1];
    int degn = end - beg;

    // ---- self loop (ep = lraw@M + bep, or exactly 0 when no in-edges) ----
    float4 lr1 = *(const float4*)&g_lraw[d * 8];
    float4 lr2 = *(const float4*)&g_lraw[d * 8 + 4];
    u64 ep0 = (degn > 0) ? bepp.x : 0ULL;
    u64 ep1 = (degn > 0) ? bepp.y : 0ULL;
    {
        float rk[8] = {lr1.x, lr1.y, lr1.z, lr1.w, lr2.x, lr2.y, lr2.z, lr2.w};
#pragma unroll
        for (int k = 0; k < 8; k++) {
            u64 rp = splat2(rk[k]);
            ulonglong2 mv = *(const ulonglong2*)&Ms[k * kD + j0];
            ep0 = fma2(rp, mv.x, ep0);
            ep1 = fma2(rp, mv.y, ep1);
        }
    }
    float4 xld = *(const float4*)&g_xl[d * kD + j0];
    u64 xldp0 = pack2(xld.x, xld.y), xldp1 = pack2(xld.z, xld.w);
    u64 v0 = add2(add2(xldp0, xrp.x), ep0);
    u64 v1 = add2(add2(xldp1, xrp.y), ep1);
    float vx, vy, vz, vw;
    unpack2(v0, vx, vy); unpack2(v1, vz, vw);
    vx = fmaxf(vx, 0.2f * vx); vy = fmaxf(vy, 0.2f * vy);
    vz = fmaxf(vz, 0.2f * vz); vw = fmaxf(vw, 0.2f * vw);
    float l = vx * attv.x + vy * attv.y + vz * attv.z + vw * attv.w;
    l += __shfl_xor_sync(0xffffffffu, l, 1);
    l += __shfl_xor_sync(0xffffffffu, l, 2);

    float m = l, den = 1.f;
    u64 acc0 = xldp0, acc1 = xldp1;

    // ---- pipelined edge loop ----
    float4 xls_n = {}, ra_n = {}, rb_n = {};
    if (beg < end) {
        int s0 = g_csrc[beg], e0 = g_ceid[beg];
        xls_n = *(const float4*)&g_xl[s0 * kD + j0];
        ra_n = *(const float4*)&eattr[(size_t)e0 * 8];
        rb_n = *(const float4*)&eattr[(size_t)e0 * 8 + 4];
    }
    for (int idx = beg; idx < end; idx++) {
        float4 xls = xls_n, ra = ra_n, rb = rb_n;
        if (idx + 1 < end) {
            int s2 = g_csrc[idx + 1], e2 = g_ceid[idx + 1];
            xls_n = *(const float4*)&g_xl[s2 * kD + j0];
            ra_n = *(const float4*)&eattr[(size_t)e2 * 8];
            rb_n = *(const float4*)&eattr[(size_t)e2 * 8 + 4];
        }
        u64 e0p = bepp.x, e1p = bepp.y;
        float rk[8] = {ra.x, ra.y, ra.z, ra.w, rb.x, rb.y, rb.z, rb.w};
#pragma unroll
        for (int k = 0; k < 8; k++) {
            u64 rp = splat2(rk[k]);
            ulonglong2 mv = *(const ulonglong2*)&Ms[k * kD + j0];
            e0p = fma2(rp, mv.x, e0p);
            e1p = fma2(rp, mv.y, e1p);
        }
        u64 xlsp0 = pack2(xls.x, xls.y), xlsp1 = pack2(xls.z, xls.w);
        u64 w0 = add2(add2(xlsp0, xrp.x), e0p);
        u64 w1 = add2(add2(xlsp1, xrp.y), e1p);
        float ax, ay, az, aw;
        unpack2(w0, ax, ay); unpack2(w1, az, aw);
        ax = fmaxf(ax, 0.2f * ax); ay = fmaxf(ay, 0.2f * ay);
        az = fmaxf(az, 0.2f * az); aw = fmaxf(aw, 0.2f * aw);
        float l2 = ax * attv.x + ay * attv.y + az * attv.z + aw * attv.w;
        l2 += __shfl_xor_sync(0xffffffffu, l2, 1);
        l2 += __shfl_xor_sync(0xffffffffu, l2, 2);

        float nm = fmaxf(m, l2);
        float sc = __expf(m - nm);
        float p  = __expf(l2 - nm);
        m = nm;
        den = den * sc + p;
        u64 scp = splat2(sc), pp = splat2(p);
        acc0 = fma2(pp, xlsp0, mul2(acc0, scp));
        acc1 = fma2(pp, xlsp1, mul2(acc1, scp));
    }

    float inv = 1.f / den;
    float4 gb = *(const float4*)&gbias[layer * kD + j0];
    float4 gm = *(const float4*)&gam[layer * kD + j0];
    float4 bt = *(const float4*)&bet[layer * kD + j0];
    float a0, a1, a2, a3;
    unpack2(acc0, a0, a1); unpack2(acc1, a2, a3);
    float w0 = gm.x * (a0 * inv + gb.x) * kBNS + bt.x;
    float w1 = gm.y * (a1 * inv + gb.y) * kBNS + bt.y;
    float w2 = gm.z * (a2 * inv + gb.z) * kBNS + bt.z;
    float w3 = gm.w * (a3 * inv + gb.w) * kBNS + bt.w;
    float4 o;
    o.x = w0 > 0.f ? w0 : expm1f(w0);
    o.y = w1 > 0.f ? w1 : expm1f(w1);
    o.z = w2 > 0.f ? w2 : expm1f(w2);
    o.w = w3 > 0.f ? w3 : expm1f(w3);
    *(float4*)&g_x[d * kD + j0] = o;
}

// ---------------- pool (batch sorted -> per-graph binary search) ------------
__global__ void pool(const int* __restrict__ batch) {
    int g = blockIdx.x;
    int t = threadIdx.x;   // 128
    __shared__ int slo, shi;
    if (t == 0) {
        int lo = 0, hi = kN;
        while (lo < hi) { int mid = (lo + hi) >> 1; if (batch[mid] < g) lo = mid + 1; else hi = mid; }
        slo = lo;
        hi = kN;
        while (lo < hi) { int mid = (lo + hi) >> 1; if (batch[mid] < g + 1) lo = mid + 1; else hi = mid; }
        shi = lo;
    }
    __syncthreads();
    int lo = slo, hi = shi;
    float s = 0.f;
    for (int n = lo; n < hi; n++) s += g_x[n * kD + t];
    g_gsum[g * kD + t] = s / fmaxf((float)(hi - lo), 1.f);
}

__global__ void head(const float* __restrict__ hW, const float* __restrict__ hb,
                     float* __restrict__ out) {
    int g = blockIdx.x;
    int lane = threadIdx.x;
    float acc[kNC] = {};
    for (int k = lane; k < kD; k += 32) {
        float mm = g_gsum[g * kD + k];
#pragma unroll
        for (int c = 0; c < kNC; c++) acc[c] += mm * hW[k * kNC + c];
    }
#pragma unroll
    for (int c = 0; c < kNC; c++) {
        float v = acc[c];
#pragma unroll
        for (int o = 16; o > 0; o >>= 1) v += __shfl_down_sync(0xffffffffu, v, o);
        if (lane == 0) out[g * kNC + c] = v + hb[c];
    }
}

// ---------------- launch -----------------------------------------------------
extern "C" void kernel_launch(void* const* d_in, const int* in_sizes, int n_in,
                              void* d_out, int out_size) {
    const int*   x_nodes = (const int*)d_in[0];
    const int*   esrc    = (const int*)d_in[1];
    const int*   edst    = (const int*)d_in[2];
    const float* eattr   = (const float*)d_in[3];
    const int*   batch   = (const int*)d_in[4];
    const float* nemb    = (const float*)d_in[5];
    const float* edge_W  = (const float*)d_in[6];
    const float* edge_b  = (const float*)d_in[7];
    const float* Wl      = (const float*)d_in[8];
    const float* bl      = (const float*)d_in[9];
    const float* Wr      = (const float*)d_in[10];
    const float* br      = (const float*)d_in[11];
    const float* We      = (const float*)d_in[12];
    const float* att     = (const float*)d_in[13];
    const float* gbias   = (const float*)d_in[14];
    const float* bng     = (const float*)d_in[15];
    const float* bnb     = (const float*)d_in[16];
    const float* headW   = (const float*)d_in[17];
    const float* headb   = (const float*)d_in[18];
    float* out = (float*)d_out;

    zero_init_kernel<<<256, 256>>>();
    node_encode<<<(kN * kD + 255) / 256, 256>>>(x_nodes, nemb);
    count_deg<<<(kE + 255) / 256, 256>>>(esrc, edst);
    scan1<<<kSB, 1024>>>();
    scan2<<<1, 32>>>();
    scan3<<<(kN + 255) / 256, 256>>>();
    scatter_csr<<<(kE + 255) / 256, 256>>>(esrc, edst);
    lraw_from_csr<<<(kN * 8 + 255) / 256, 256>>>(eattr);
    make_M_all<<<kL, 1024>>>(edge_W, edge_b, We);

    for (int i = 0; i < kL; i++) {
        xlr_gemm<<<dim3((kN + 31) / 32, 2), 256>>>(Wl, bl, Wr, br, i);
        fused_gat<<<(kN * 32 + 255) / 256, 256>>>(eattr, att, gbias, bng, bnb, i);
    }

    pool<<<kG, kD>>>(batch);
    head<<<kG, 32>>>(headW, headb, out);
}

// round 4
// speedup vs baseline: 1.1146x; 1.1146x over previous
#include <cuda_runtime.h>
#include <math.h>

constexpr int kN   = 50000;
constexpr int kE   = 800000;
constexpr int kG   = 512;
constexpr int kD   = 128;
constexpr int kEE  = 64;
constexpr int kL   = 4;
constexpr int kNC  = 10;
constexpr int kSB  = (kN + 1023) / 1024;
constexpr float kBNS = 0.9999950000374997f;  // (1+1e-5)^-0.5

typedef unsigned long long u64;

// ---------------- f32x2 packed helpers -------------------------------------
__device__ __forceinline__ u64 pack2(float lo, float hi) {
    u64 r; asm("mov.b64 %0,{%1,%2};" : "=l"(r) : "f"(lo), "f"(hi)); return r;
}
__device__ __forceinline__ u64 splat2(float v) { return pack2(v, v); }
__device__ __forceinline__ void unpack2(u64 p, float& lo, float& hi) {
    asm("mov.b64 {%0,%1},%2;" : "=f"(lo), "=f"(hi) : "l"(p));
}
__device__ __forceinline__ u64 fma2(u64 a, u64 b, u64 c) {
    u64 r; asm("fma.rn.f32x2 %0,%1,%2,%3;" : "=l"(r) : "l"(a), "l"(b), "l"(c)); return r;
}
__device__ __forceinline__ u64 add2(u64 a, u64 b) {
    u64 r; asm("add.rn.f32x2 %0,%1,%2;" : "=l"(r) : "l"(a), "l"(b)); return r;
}

// ---------------- scratch ----------------------------------------------------
__device__ float g_x[kN * kD];
__device__ float g_xl[kN * kD];
__device__ float g_xr[kN * kD];
__device__ float g_lraw[kN * 8];
__device__ int   g_deg[kN];
__device__ int   g_cur[kN];
__device__ int   g_off[kN + 1];
__device__ int   g_csrc[kE];
__device__ float g_eraw[(size_t)kE * 8];   // raw edge attrs permuted to CSR order
__device__ float g_M[kL * 8 * kD];
__device__ float g_bep[kL * kD];
__device__ float g_gsum[kG * kD];

// ---------------- 1: init (zero + node encode) -------------------------------
__global__ void init_enc(const int* __restrict__ xn, const float* __restrict__ emb) {
    int i = blockIdx.x * blockDim.x + threadIdx.x;
    int stride = gridDim.x * blockDim.x;
    for (int t = i; t < kN; t += stride) { g_deg[t] = 0; g_cur[t] = 0; }
    for (int t = i; t < kN * kD; t += stride) {
        int n = t >> 7, j = t & 127;
        g_x[t] = emb[xn[n] * kD + j];
    }
}

// ---------------- 2: degree count --------------------------------------------
__global__ void count_deg(const int* __restrict__ src, const int* __restrict__ dst) {
    int e = blockIdx.x * blockDim.x + threadIdx.x;
    if (e >= kE) return;
    int s = src[e], d = dst[e];
    if (s != d) atomicAdd(&g_deg[d], 1);
}

// ---------------- 3: single-block exclusive scan -----------------------------
__global__ void scan_single() {
    __shared__ int sh[1024];
    __shared__ int run;
    int t = threadIdx.x;
    if (t == 0) run = 0;
    __syncthreads();
    for (int c = 0; c < kSB; c++) {
        int n = c * 1024 + t;
        int v = (n < kN) ? g_deg[n] : 0;
        sh[t] = v;
        __syncthreads();
        for (int o = 1; o < 1024; o <<= 1) {
            int a = (t >= o) ? sh[t - o] : 0;
            __syncthreads();
            sh[t] += a;
            __syncthreads();
        }
        if (n < kN) g_off[n] = run + sh[t] - v;
        int last = sh[1023];
        __syncthreads();
        if (t == 0) run += last;
        __syncthreads();
    }
    if (t == 0) g_off[kN] = run;
}

// ---------------- 4 (PROFILED): xl/xr GEMM, 64-node x 128-col tiles ----------
__global__ __launch_bounds__(256) void xlr_gemm(
        const float* __restrict__ Wl, const float* __restrict__ bl,
        const float* __restrict__ Wr, const float* __restrict__ br, int layer) {
    const float* W = (blockIdx.y == 0 ? Wl : Wr) + layer * kD * kD;
    const float* bias = (blockIdx.y == 0 ? bl : br) + layer * kD;
    float* out = blockIdx.y == 0 ? g_xl : g_xr;

    __shared__ __align__(16) float ws[32 * 128];   // 16 KB
    __shared__ float xs[64][33];                   // 8.4 KB

    int t = threadIdx.x;        // 256
    int lane = t & 31;          // col group: lane*4
    int w = t >> 5;             // warp: nodes w*8 .. w*8+7
    int n0 = blockIdx.x * 64;

    u64 acc[8][2] = {};
    for (int kt = 0; kt < kD; kt += 32) {
#pragma unroll
        for (int r = t; r < 32 * 128; r += 256)
            ws[r] = W[(kt + (r >> 7)) * kD + (r & 127)];
#pragma unroll
        for (int r = t; r < 64 * 32; r += 256) {
            int n = r >> 5, kk = r & 31;
            int nn = n0 + n;
            xs[n][kk] = (nn < kN) ? g_x[nn * kD + kt + kk] : 0.f;
        }
        __syncthreads();
#pragma unroll
        for (int kk = 0; kk < 32; kk++) {
            ulonglong2 wv = *(const ulonglong2*)&ws[kk * 128 + lane * 4];
#pragma unroll
            for (int m = 0; m < 8; m++) {
                u64 xp = splat2(xs[w * 8 + m][kk]);
                acc[m][0] = fma2(xp, wv.x, acc[m][0]);
                acc[m][1] = fma2(xp, wv.y, acc[m][1]);
            }
        }
        __syncthreads();
    }
    float4 bv = *(const float4*)(bias + lane * 4);
#pragma unroll
    for (int m = 0; m < 8; m++) {
        int n = n0 + w * 8 + m;
        if (n < kN) {
            float a0, a1, a2, a3;
            unpack2(acc[m][0], a0, a1);
            unpack2(acc[m][1], a2, a3);
            float4 o = make_float4(a0 + bv.x, a1 + bv.y, a2 + bv.z, a3 + bv.w);
            *(float4*)&out[n * kD + lane * 4] = o;
        }
    }
}

// ---------------- 5: scatter CSR + permute raw edge attrs -------------------
__global__ void scatter_csr(const int* __restrict__ src, const int* __restrict__ dst,
                            const float* __restrict__ eattr) {
    int e = blockIdx.x * blockDim.x + threadIdx.x;
    if (e >= kE) return;
    int s = src[e], d = dst[e];
    if (s == d) return;
    int pos = atomicAdd(&g_cur[d], 1);
    int idx = g_off[d] + pos;
    g_csrc[idx] = s;
    float4 a = *(const float4*)&eattr[(size_t)e * 8];
    float4 b = *(const float4*)&eattr[(size_t)e * 8 + 4];
    *(float4*)&g_eraw[(size_t)idx * 8] = a;
    *(float4*)&g_eraw[(size_t)idx * 8 + 4] = b;
}

// ---------------- 6: lraw (mean raw attrs per dst) + M/bep for all layers ---
__global__ void prep(const float* __restrict__ eW, const float* __restrict__ eb,
                     const float* __restrict__ We) {
    int nbl = (kN * 8 + 1023) / 1024;   // lraw blocks
    if ((int)blockIdx.x < nbl) {
        int t = blockIdx.x * 1024 + threadIdx.x;
        int n = t >> 3, j = t & 7;
        if (n >= kN) return;
        int beg = g_off[n], end = g_off[n + 1];
        float s = 0.f;
        for (int idx = beg; idx < end; idx++) s += g_eraw[(size_t)idx * 8 + j];
        int c = end - beg;
        g_lraw[n * 8 + j] = s / (float)(c > 1 ? c : 1);
    } else {
        int layer = blockIdx.x - nbl;
        int t = threadIdx.x;          // 1024
        int k = t >> 7, j = t & 127;
        const float* w = We + (size_t)layer * kEE * kD;
        float acc = 0.f;
#pragma unroll 8
        for (int u = 0; u < kEE; u++) acc += eW[k * kEE + u] * w[u * kD + j];
        g_M[layer * 8 * kD + k * kD + j] = acc;
        if (t < kD) {
            float b = 0.f;
#pragma unroll 8
            for (int u = 0; u < kEE; u++) b += eb[u] * w[u * kD + t];
            g_bep[layer * kD + t] = b;
        }
    }
}

// ---------------- fused GAT layer (M in registers, deep pipeline) -----------
__global__ __launch_bounds__(256) void fused_gat(
        const float* __restrict__ att, const float* __restrict__ gbias,
        const float* __restrict__ gam, const float* __restrict__ bet, int layer) {
    int t = threadIdx.x, lane = t & 31;
    int d = (blockIdx.x * 256 + t) >> 5;
    if (d >= kN) return;
    int j0 = lane * 4;

    // M[8][4] for this lane's columns, in registers
    u64 Mr[8][2];
#pragma unroll
    for (int k = 0; k < 8; k++) {
        float4 mv = *(const float4*)&g_M[layer * 8 * kD + k * kD + j0];
        Mr[k][0] = pack2(mv.x, mv.y);
        Mr[k][1] = pack2(mv.z, mv.w);
    }
    float4 attv = *(const float4*)&att[layer * kD + j0];
    float4 bep4 = *(const float4*)&g_bep[layer * kD + j0];
    float4 xld4 = *(const float4*)&g_xl[d * kD + j0];
    u64 xld0 = pack2(xld4.x, xld4.y), xld1 = pack2(xld4.z, xld4.w);

    int beg = g_off[d], end = g_off[d + 1];

    float4 gb = *(const float4*)&gbias[layer * kD + j0];
    float4 gm = *(const float4*)&gam[layer * kD + j0];
    float4 bt = *(const float4*)&bet[layer * kD + j0];

    float a0, a1, a2, a3;
    if (beg == end) {
        // no incoming edges: softmax over the single self loop == 1
        a0 = xld4.x; a1 = xld4.y; a2 = xld4.z; a3 = xld4.w;
    } else {
        float4 xr4 = *(const float4*)&g_xr[d * kD + j0];
        // xrb = xr + bep (per-edge constant part)
        u64 xrb0 = pack2(xr4.x + bep4.x, xr4.y + bep4.y);
        u64 xrb1 = pack2(xr4.z + bep4.z, xr4.w + bep4.w);

        // ---- self loop logit: leaky(xl_d + xr_d + lraw@M + bep) . att ----
        float4 lr1 = *(const float4*)&g_lraw[d * 8];
        float4 lr2 = *(const float4*)&g_lraw[d * 8 + 4];
        u64 e0 = xrb0, e1 = xrb1;
        {
            float rk[8] = {lr1.x, lr1.y, lr1.z, lr1.w, lr2.x, lr2.y, lr2.z, lr2.w};
#pragma unroll
            for (int k = 0; k < 8; k++) {
                u64 rp = splat2(rk[k]);
                e0 = fma2(rp, Mr[k][0], e0);
                e1 = fma2(rp, Mr[k][1], e1);
            }
        }
        u64 v0 = add2(xld0, e0), v1 = add2(xld1, e1);
        float vx, vy, vz, vw;
        unpack2(v0, vx, vy); unpack2(v1, vz, vw);
        vx = fmaxf(vx, 0.2f * vx); vy = fmaxf(vy, 0.2f * vy);
        vz = fmaxf(vz, 0.2f * vz); vw = fmaxf(vw, 0.2f * vw);
        float l = vx * attv.x + vy * attv.y + vz * attv.z + vw * attv.w;
        l += __shfl_xor_sync(0xffffffffu, l, 1);
        l += __shfl_xor_sync(0xffffffffu, l, 2);

        float m = l, den = 1.f;
        u64 acc0 = xld0, acc1 = xld1;

        // ---- pipelined edge loop: 2-deep for (src,raw), 1-deep for xl ----
        int s1 = 0, s2 = 0;
        float4 ra1 = {}, rb1 = {}, ra2 = {}, rb2 = {}, xl1 = {};
        s1 = g_csrc[beg];
        ra1 = *(const float4*)&g_eraw[(size_t)beg * 8];
        rb1 = *(const float4*)&g_eraw[(size_t)beg * 8 + 4];
        xl1 = *(const float4*)&g_xl[s1 * kD + j0];
        if (beg + 1 < end) {
            s2 = g_csrc[beg + 1];
            ra2 = *(const float4*)&g_eraw[(size_t)(beg + 1) * 8];
            rb2 = *(const float4*)&g_eraw[(size_t)(beg + 1) * 8 + 4];
        }
        for (int idx = beg; idx < end; idx++) {
            float4 ra = ra1, rb = rb1, xls = xl1;
            // advance pipeline (all loads address-ready)
            if (idx + 1 < end) {
                xl1 = *(const float4*)&g_xl[s2 * kD + j0];
                s1 = s2; ra1 = ra2; rb1 = rb2;
            }
            if (idx + 2 < end) {
                s2 = g_csrc[idx + 2];
                ra2 = *(const float4*)&g_eraw[(size_t)(idx + 2) * 8];
                rb2 = *(const float4*)&g_eraw[(size_t)(idx + 2) * 8 + 4];
            }
            u64 f0 = xrb0, f1 = xrb1;
            float rk[8] = {ra.x, ra.y, ra.z, ra.w, rb.x, rb.y, rb.z, rb.w};
#pragma unroll
            for (int k = 0; k < 8; k++) {
                u64 rp = splat2(rk[k]);
                f0 = fma2(rp, Mr[k][0], f0);
                f1 = fma2(rp, Mr[k][1], f1);
            }
            u64 xlsp0 = pack2(xls.x, xls.y), xlsp1 = pack2(xls.z, xls.w);
            u64 w0 = add2(xlsp0, f0), w1 = add2(xlsp1, f1);
            float ax, ay, az, aw;
            unpack2(w0, ax, ay); unpack2(w1, az, aw);
            ax = fmaxf(ax, 0.2f * ax); ay = fmaxf(ay, 0.2f * ay);
            az = fmaxf(az, 0.2f * az); aw = fmaxf(aw, 0.2f * aw);
            float l2 = ax * attv.x + ay * attv.y + az * attv.z + aw * attv.w;
            l2 += __shfl_xor_sync(0xffffffffu, l2, 1);
            l2 += __shfl_xor_sync(0xffffffffu, l2, 2);

            if (l2 > m) {             // warp-uniform branch
                float sc = __expf(m - l2);
                den = den * sc + 1.f;
                u64 scp = splat2(sc);
                acc0 = fma2(acc0, scp, xlsp0);
                acc1 = fma2(acc1, scp, xlsp1);
                m = l2;
            } else {
                float p = __expf(l2 - m);
                den += p;
                u64 pp = splat2(p);
                acc0 = fma2(pp, xlsp0, acc0);
                acc1 = fma2(pp, xlsp1, acc1);
            }
        }
        float inv = 1.f / den;
        float c0, c1, c2, c3;
        unpack2(acc0, c0, c1); unpack2(acc1, c2, c3);
        a0 = c0 * inv; a1 = c1 * inv; a2 = c2 * inv; a3 = c3 * inv;
    }

    float w0 = gm.x * (a0 + gb.x) * kBNS + bt.x;
    float w1 = gm.y * (a1 + gb.y) * kBNS + bt.y;
    float w2 = gm.z * (a2 + gb.z) * kBNS + bt.z;
    float w3 = gm.w * (a3 + gb.w) * kBNS + bt.w;
    float4 o;
    o.x = w0 > 0.f ? w0 : expm1f(w0);
    o.y = w1 > 0.f ? w1 : expm1f(w1);
    o.z = w2 > 0.f ? w2 : expm1f(w2);
    o.w = w3 > 0.f ? w3 : expm1f(w3);
    *(float4*)&g_x[d * kD + j0] = o;
}

// ---------------- pool + head ------------------------------------------------
__global__ void pool(const int* __restrict__ batch) {
    int g = blockIdx.x;
    int t = threadIdx.x;   // 128
    __shared__ int slo, shi;
    if (t == 0) {
        int lo = 0, hi = kN;
        while (lo < hi) { int mid = (lo + hi) >> 1; if (batch[mid] < g) lo = mid + 1; else hi = mid; }
        slo = lo;
        hi = kN;
        while (lo < hi) { int mid = (lo + hi) >> 1; if (batch[mid] < g + 1) lo = mid + 1; else hi = mid; }
        shi = lo;
    }
    __syncthreads();
    int lo = slo, hi = shi;
    float s = 0.f;
    for (int n = lo; n < hi; n++) s += g_x[n * kD + t];
    g_gsum[g * kD + t] = s / fmaxf((float)(hi - lo), 1.f);
}

__global__ void head(const float* __restrict__ hW, const float* __restrict__ hb,
                     float* __restrict__ out) {
    int g = blockIdx.x;
    int lane = threadIdx.x;
    float acc[kNC] = {};
    for (int k = lane; k < kD; k += 32) {
        float mm = g_gsum[g * kD + k];
#pragma unroll
        for (int c = 0; c < kNC; c++) acc[c] += mm * hW[k * kNC + c];
    }
#pragma unroll
    for (int c = 0; c < kNC; c++) {
        float v = acc[c];
#pragma unroll
        for (int o = 16; o > 0; o >>= 1) v += __shfl_down_sync(0xffffffffu, v, o);
        if (lane == 0) out[g * kNC + c] = v + hb[c];
    }
}

// ---------------- launch -----------------------------------------------------
extern "C" void kernel_launch(void* const* d_in, const int* in_sizes, int n_in,
                              void* d_out, int out_size) {
    const int*   x_nodes = (const int*)d_in[0];
    const int*   esrc    = (const int*)d_in[1];
    const int*   edst    = (const int*)d_in[2];
    const float* eattr   = (const float*)d_in[3];
    const int*   batch   = (const int*)d_in[4];
    const float* nemb    = (const float*)d_in[5];
    const float* edge_W  = (const float*)d_in[6];
    const float* edge_b  = (const float*)d_in[7];
    const float* Wl      = (const float*)d_in[8];
    const float* bl      = (const float*)d_in[9];
    const float* Wr      = (const float*)d_in[10];
    const float* br      = (const float*)d_in[11];
    const float* We      = (const float*)d_in[12];
    const float* att     = (const float*)d_in[13];
    const float* gbias   = (const float*)d_in[14];
    const float* bng     = (const float*)d_in[15];
    const float* bnb     = (const float*)d_in[16];
    const float* headW   = (const float*)d_in[17];
    const float* headb   = (const float*)d_in[18];
    float* out = (float*)d_out;

    init_enc<<<4096, 256>>>(x_nodes, nemb);                       // 1
    count_deg<<<(kE + 255) / 256, 256>>>(esrc, edst);             // 2
    scan_single<<<1, 1024>>>();                                   // 3
    xlr_gemm<<<dim3((kN + 63) / 64, 2), 256>>>(Wl, bl, Wr, br, 0); // 4 (profiled)
    scatter_csr<<<(kE + 255) / 256, 256>>>(esrc, edst, eattr);    // 5
    int nbl = (kN * 8 + 1023) / 1024;
    prep<<<nbl + kL, 1024>>>(edge_W, edge_b, We);                 // 6
    fused_gat<<<(kN * 32 + 255) / 256, 256>>>(att, gbias, bng, bnb, 0);

    for (int i = 1; i < kL; i++) {
        xlr_gemm<<<dim3((kN + 63) / 64, 2), 256>>>(Wl, bl, Wr, br, i);
        fused_gat<<<(kN * 32 + 255) / 256, 256>>>(att, gbias, bng, bnb, i);
    }

    pool<<<kG, kD>>>(batch);
    head<<<kG, 32>>>(headW, headb, out);
}

// round 5
// speedup vs baseline: 1.2662x; 1.1360x over previous
#include <cuda_runtime.h>
#include <math.h>

constexpr int kN   = 50000;
constexpr int kE   = 800000;
constexpr int kG   = 512;
constexpr int kD   = 128;
constexpr int kEE  = 64;
constexpr int kL   = 4;
constexpr int kNC  = 10;
constexpr int kSB  = (kN + 1023) / 1024;
constexpr float kBNS = 0.9999950000374997f;  // (1+1e-5)^-0.5

typedef unsigned long long u64;

// ---------------- f32x2 packed helpers -------------------------------------
__device__ __forceinline__ u64 pack2(float lo, float hi) {
    u64 r; asm("mov.b64 %0,{%1,%2};" : "=l"(r) : "f"(lo), "f"(hi)); return r;
}
__device__ __forceinline__ u64 splat2(float v) { return pack2(v, v); }
__device__ __forceinline__ void unpack2(u64 p, float& lo, float& hi) {
    asm("mov.b64 {%0,%1},%2;" : "=f"(lo), "=f"(hi) : "l"(p));
}
__device__ __forceinline__ u64 fma2(u64 a, u64 b, u64 c) {
    u64 r; asm("fma.rn.f32x2 %0,%1,%2,%3;" : "=l"(r) : "l"(a), "l"(b), "l"(c)); return r;
}
__device__ __forceinline__ u64 add2(u64 a, u64 b) {
    u64 r; asm("add.rn.f32x2 %0,%1,%2;" : "=l"(r) : "l"(a), "l"(b)); return r;
}
__device__ __forceinline__ u64 mul2(u64 a, u64 b) {
    u64 r; asm("mul.rn.f32x2 %0,%1,%2;" : "=l"(r) : "l"(a), "l"(b)); return r;
}

// ---------------- scratch ----------------------------------------------------
__device__ float g_x[kN * kD];
__device__ float g_xl[kN * kD];
__device__ float g_xr[kN * kD];
__device__ float g_lraw[kN * 8];
__device__ int   g_deg[kN];
__device__ int   g_cur[kN];
__device__ int   g_scan[kN];
__device__ int   g_bt[kSB];
__device__ int   g_boff[kSB];
__device__ int   g_off[kN + 1];
__device__ int   g_csrc[kE];
__device__ float g_eraw[(size_t)kE * 8];
__device__ float g_M[kL * 8 * kD];
__device__ float g_bep[kL * kD];
__device__ float g_gsum[kG * kD];

// ---------------- 1: init + node encode --------------------------------------
__global__ void init_enc(const int* __restrict__ xn, const float* __restrict__ emb) {
    int i = blockIdx.x * blockDim.x + threadIdx.x;
    int stride = gridDim.x * blockDim.x;
    for (int t = i; t < kN; t += stride) { g_deg[t] = 0; g_cur[t] = 0; }
    for (int t = i; t < kN * kD; t += stride) {
        int n = t >> 7, j = t & 127;
        g_x[t] = emb[xn[n] * kD + j];
    }
}

// ---------------- 2: degree count --------------------------------------------
__global__ void count_deg(const int* __restrict__ src, const int* __restrict__ dst) {
    int e = blockIdx.x * blockDim.x + threadIdx.x;
    if (e >= kE) return;
    int s = src[e], d = dst[e];
    if (s != d) atomicAdd(&g_deg[d], 1);
}

// ---------------- 3/5/6: multi-block scan ------------------------------------
__global__ void scan1() {
    __shared__ int sh[1024];
    int n = blockIdx.x * 1024 + threadIdx.x;
    int v = (n < kN) ? g_deg[n] : 0;
    sh[threadIdx.x] = v;
    __syncthreads();
    for (int o = 1; o < 1024; o <<= 1) {
        int add = (threadIdx.x >= o) ? sh[threadIdx.x - o] : 0;
        __syncthreads();
        sh[threadIdx.x] += add;
        __syncthreads();
    }
    if (n < kN) g_scan[n] = sh[threadIdx.x];
    if (threadIdx.x == 1023) g_bt[blockIdx.x] = sh[1023];
}
__global__ void scan2() {
    if (threadIdx.x == 0) {
        int run = 0;
        for (int b = 0; b < kSB; b++) { g_boff[b] = run; run += g_bt[b]; }
        g_off[kN] = run;
    }
}
__global__ void scan3() {
    int n = blockIdx.x * blockDim.x + threadIdx.x;
    if (n < kN) g_off[n] = g_scan[n] - g_deg[n] + g_boff[n >> 10];
}

// ---------------- 4 (PROFILED): xl/xr GEMM, xs transposed --------------------
__global__ __launch_bounds__(256) void xlr_gemm(
        const float* __restrict__ Wl, const float* __restrict__ bl,
        const float* __restrict__ Wr, const float* __restrict__ br, int layer) {
    const float* W = (blockIdx.y == 0 ? Wl : Wr) + layer * kD * kD;
    const float* bias = (blockIdx.y == 0 ? bl : br) + layer * kD;
    float* out = blockIdx.y == 0 ? g_xl : g_xr;

    __shared__ __align__(16) float ws[32 * 128];   // 16 KB
    __shared__ __align__(16) float xs[32][68];     // transposed [kk][node], pad 68

    int t = threadIdx.x;        // 256
    int lane = t & 31;          // col group: lane*4
    int w = t >> 5;             // warp: nodes w*8 .. w*8+7
    int n0 = blockIdx.x * 64;

    u64 acc[8][2] = {};
    for (int kt = 0; kt < kD; kt += 32) {
#pragma unroll
        for (int r = t; r < 32 * 128; r += 256)
            ws[r] = W[(kt + (r >> 7)) * kD + (r & 127)];
#pragma unroll
        for (int r = t; r < 64 * 32; r += 256) {
            int n = r >> 5, kk = r & 31;     // warp: 32 consecutive kk, same n
            int nn = n0 + n;
            xs[kk][n] = (nn < kN) ? g_x[nn * kD + kt + kk] : 0.f;
        }
        __syncthreads();
#pragma unroll
        for (int kk = 0; kk < 32; kk++) {
            ulonglong2 wv = *(const ulonglong2*)&ws[kk * 128 + lane * 4];
            float4 xv0 = *(const float4*)&xs[kk][w * 8];       // broadcast
            float4 xv1 = *(const float4*)&xs[kk][w * 8 + 4];   // broadcast
            float xm[8] = {xv0.x, xv0.y, xv0.z, xv0.w, xv1.x, xv1.y, xv1.z, xv1.w};
#pragma unroll
            for (int m = 0; m < 8; m++) {
                u64 xp = splat2(xm[m]);
                acc[m][0] = fma2(xp, wv.x, acc[m][0]);
                acc[m][1] = fma2(xp, wv.y, acc[m][1]);
            }
        }
        __syncthreads();
    }
    float4 bv = *(const float4*)(bias + lane * 4);
#pragma unroll
    for (int m = 0; m < 8; m++) {
        int n = n0 + w * 8 + m;
        if (n < kN) {
            float a0, a1, a2, a3;
            unpack2(acc[m][0], a0, a1);
            unpack2(acc[m][1], a2, a3);
            float4 o = make_float4(a0 + bv.x, a1 + bv.y, a2 + bv.z, a3 + bv.w);
            *(float4*)&out[n * kD + lane * 4] = o;
        }
    }
}

// ---------------- 7: scatter CSR + permute raw edge attrs -------------------
__global__ void scatter_csr(const int* __restrict__ src, const int* __restrict__ dst,
                            const float* __restrict__ eattr) {
    int e = blockIdx.x * blockDim.x + threadIdx.x;
    if (e >= kE) return;
    int s = src[e], d = dst[e];
    if (s == d) return;
    int pos = atomicAdd(&g_cur[d], 1);
    int idx = g_off[d] + pos;
    g_csrc[idx] = s;
    float4 a = *(const float4*)&eattr[(size_t)e * 8];
    float4 b = *(const float4*)&eattr[(size_t)e * 8 + 4];
    *(float4*)&g_eraw[(size_t)idx * 8] = a;
    *(float4*)&g_eraw[(size_t)idx * 8 + 4] = b;
}

// ---------------- 8: lraw + M/bep for all layers ----------------------------
__global__ void prep(const float* __restrict__ eW, const float* __restrict__ eb,
                     const float* __restrict__ We) {
    int nbl = (kN * 8 + 1023) / 1024;
    if ((int)blockIdx.x < nbl) {
        int t = blockIdx.x * 1024 + threadIdx.x;
        int n = t >> 3, j = t & 7;
        if (n >= kN) return;
        int beg = g_off[n], end = g_off[n + 1];
        float s = 0.f;
        for (int idx = beg; idx < end; idx++) s += g_eraw[(size_t)idx * 8 + j];
        int c = end - beg;
        g_lraw[n * 8 + j] = s / (float)(c > 1 ? c : 1);
    } else {
        int layer = blockIdx.x - nbl;
        int t = threadIdx.x;
        int k = t >> 7, j = t & 127;
        const float* w = We + (size_t)layer * kEE * kD;
        float acc = 0.f;
#pragma unroll 8
        for (int u = 0; u < kEE; u++) acc += eW[k * kEE + u] * w[u * kD + j];
        g_M[layer * 8 * kD + k * kD + j] = acc;
        if (t < kD) {
            float b = 0.f;
#pragma unroll 8
            for (int u = 0; u < kEE; u++) b += eb[u] * w[u * kD + t];
            g_bep[layer * kD + t] = b;
        }
    }
}

// ---------------- fused GAT layer (pair-unrolled online softmax) ------------
__global__ __launch_bounds__(128) void fused_gat(
        const float* __restrict__ att, const float* __restrict__ gbias,
        const float* __restrict__ gam, const float* __restrict__ bet, int layer) {
    int t = threadIdx.x, lane = t & 31;
    int d = (blockIdx.x * 128 + t) >> 5;
    if (d >= kN) return;
    int j0 = lane * 4;

    u64 Mr[8][2];
#pragma unroll
    for (int k = 0; k < 8; k++) {
        float4 mv = *(const float4*)&g_M[layer * 8 * kD + k * kD + j0];
        Mr[k][0] = pack2(mv.x, mv.y);
        Mr[k][1] = pack2(mv.z, mv.w);
    }
    float4 attv = *(const float4*)&att[layer * kD + j0];
    float4 bep4 = *(const float4*)&g_bep[layer * kD + j0];
    float4 xld4 = *(const float4*)&g_xl[d * kD + j0];
    u64 xld0 = pack2(xld4.x, xld4.y), xld1 = pack2(xld4.z, xld4.w);

    int beg = g_off[d], end = g_off[d + 1];

    float4 gb = *(const float4*)&gbias[layer * kD + j0];
    float4 gm = *(const float4*)&gam[layer * kD + j0];
    float4 bt = *(const float4*)&bet[layer * kD + j0];

    float a0, a1, a2, a3;
    if (beg == end) {
        a0 = xld4.x; a1 = xld4.y; a2 = xld4.z; a3 = xld4.w;
    } else {
        float4 xr4 = *(const float4*)&g_xr[d * kD + j0];
        u64 xrb0 = pack2(xr4.x + bep4.x, xr4.y + bep4.y);
        u64 xrb1 = pack2(xr4.z + bep4.z, xr4.w + bep4.w);

        // ---- self loop logit ----
        float4 lr1 = *(const float4*)&g_lraw[d * 8];
        float4 lr2 = *(const float4*)&g_lraw[d * 8 + 4];
        u64 e0 = xrb0, e1 = xrb1;
        {
            float rk[8] = {lr1.x, lr1.y, lr1.z, lr1.w, lr2.x, lr2.y, lr2.z, lr2.w};
#pragma unroll
            for (int k = 0; k < 8; k++) {
                u64 rp = splat2(rk[k]);
                e0 = fma2(rp, Mr[k][0], e0);
                e1 = fma2(rp, Mr[k][1], e1);
            }
        }
        u64 v0 = add2(xld0, e0), v1 = add2(xld1, e1);
        float vx, vy, vz, vw;
        unpack2(v0, vx, vy); unpack2(v1, vz, vw);
        vx = fmaxf(vx, 0.2f * vx); vy = fmaxf(vy, 0.2f * vy);
        vz = fmaxf(vz, 0.2f * vz); vw = fmaxf(vw, 0.2f * vw);
        float l = vx * attv.x + vy * attv.y + vz * attv.z + vw * attv.w;
        l += __shfl_xor_sync(0xffffffffu, l, 1);
        l += __shfl_xor_sync(0xffffffffu, l, 2);

        float m = l, den = 1.f;
        u64 acc0 = xld0, acc1 = xld1;

        // ---- pair-unrolled edge loop with pair-ahead prefetch ----
        int i = beg, rem = end - beg;
        int s0 = g_csrc[i];
        float4 r0a = *(const float4*)&g_eraw[(size_t)i * 8];
        float4 r0b = *(const float4*)&g_eraw[(size_t)i * 8 + 4];
        int s1 = 0; float4 r1a = {}, r1b = {};
        if (rem >= 2) {
            s1 = g_csrc[i + 1];
            r1a = *(const float4*)&g_eraw[(size_t)(i + 1) * 8];
            r1b = *(const float4*)&g_eraw[(size_t)(i + 1) * 8 + 4];
        }
        while (rem > 0) {
            int take = (rem >= 2) ? 2 : 1;
            float4 xa = *(const float4*)&g_xl[s0 * kD + j0];
            float4 xb = xa;
            if (take == 2) xb = *(const float4*)&g_xl[s1 * kD + j0];
            float4 c0a = r0a, c0b = r0b, c1a = r1a, c1b = r1b;
            int ni = i + take, nrem = rem - take;
            if (nrem > 0) {
                s0 = g_csrc[ni];
                r0a = *(const float4*)&g_eraw[(size_t)ni * 8];
                r0b = *(const float4*)&g_eraw[(size_t)ni * 8 + 4];
                if (nrem >= 2) {
                    s1 = g_csrc[ni + 1];
                    r1a = *(const float4*)&g_eraw[(size_t)(ni + 1) * 8];
                    r1b = *(const float4*)&g_eraw[(size_t)(ni + 1) * 8 + 4];
                }
            }
            // logit A
            u64 xap0 = pack2(xa.x, xa.y), xap1 = pack2(xa.z, xa.w);
            float la;
            {
                u64 f0 = xrb0, f1 = xrb1;
                float rk[8] = {c0a.x, c0a.y, c0a.z, c0a.w, c0b.x, c0b.y, c0b.z, c0b.w};
#pragma unroll
                for (int k = 0; k < 8; k++) {
                    u64 rp = splat2(rk[k]);
                    f0 = fma2(rp, Mr[k][0], f0);
                    f1 = fma2(rp, Mr[k][1], f1);
                }
                u64 w0 = add2(xap0, f0), w1 = add2(xap1, f1);
                float ax, ay, az, aw;
                unpack2(w0, ax, ay); unpack2(w1, az, aw);
                ax = fmaxf(ax, 0.2f * ax); ay = fmaxf(ay, 0.2f * ay);
                az = fmaxf(az, 0.2f * az); aw = fmaxf(aw, 0.2f * aw);
                la = ax * attv.x + ay * attv.y + az * attv.z + aw * attv.w;
                la += __shfl_xor_sync(0xffffffffu, la, 1);
                la += __shfl_xor_sync(0xffffffffu, la, 2);
            }
            if (take == 2) {
                u64 xbp0 = pack2(xb.x, xb.y), xbp1 = pack2(xb.z, xb.w);
                float lb;
                {
                    u64 f0 = xrb0, f1 = xrb1;
                    float rk[8] = {c1a.x, c1a.y, c1a.z, c1a.w, c1b.x, c1b.y, c1b.z, c1b.w};
#pragma unroll
                    for (int k = 0; k < 8; k++) {
                        u64 rp = splat2(rk[k]);
                        f0 = fma2(rp, Mr[k][0], f0);
                        f1 = fma2(rp, Mr[k][1], f1);
                    }
                    u64 w0 = add2(xbp0, f0), w1 = add2(xbp1, f1);
                    float bx, by, bz, bw;
                    unpack2(w0, bx, by); unpack2(w1, bz, bw);
                    bx = fmaxf(bx, 0.2f * bx); by = fmaxf(by, 0.2f * by);
                    bz = fmaxf(bz, 0.2f * bz); bw = fmaxf(bw, 0.2f * bw);
                    lb = bx * attv.x + by * attv.y + bz * attv.z + bw * attv.w;
                    lb += __shfl_xor_sync(0xffffffffu, lb, 1);
                    lb += __shfl_xor_sync(0xffffffffu, lb, 2);
                }
                float nm = fmaxf(m, fmaxf(la, lb));
                float sc = __expf(m - nm);
                float pa = __expf(la - nm);
                float pb = __expf(lb - nm);
                m = nm;
                den = den * sc + pa + pb;
                acc0 = fma2(splat2(pb), xbp0, fma2(splat2(pa), xap0, mul2(acc0, splat2(sc))));
                acc1 = fma2(splat2(pb), xbp1, fma2(splat2(pa), xap1, mul2(acc1, splat2(sc))));
            } else {
                float nm = fmaxf(m, la);
                float sc = __expf(m - nm);
                float pa = __expf(la - nm);
                m = nm;
                den = den * sc + pa;
                acc0 = fma2(splat2(pa), xap0, mul2(acc0, splat2(sc)));
                acc1 = fma2(splat2(pa), xap1, mul2(acc1, splat2(sc)));
            }
            i = ni; rem = nrem;
        }
        float inv = 1.f / den;
        float c0, c1, c2, c3;
        unpack2(acc0, c0, c1); unpack2(acc1, c2, c3);
        a0 = c0 * inv; a1 = c1 * inv; a2 = c2 * inv; a3 = c3 * inv;
    }

    float w0 = gm.x * (a0 + gb.x) * kBNS + bt.x;
    float w1 = gm.y * (a1 + gb.y) * kBNS + bt.y;
    float w2 = gm.z * (a2 + gb.z) * kBNS + bt.z;
    float w3 = gm.w * (a3 + gb.w) * kBNS + bt.w;
    float4 o;
    o.x = w0 > 0.f ? w0 : expm1f(w0);
    o.y = w1 > 0.f ? w1 : expm1f(w1);
    o.z = w2 > 0.f ? w2 : expm1f(w2);
    o.w = w3 > 0.f ? w3 : expm1f(w3);
    *(float4*)&g_x[d * kD + j0] = o;
}

// ---------------- pool + head ------------------------------------------------
__global__ void pool(const int* __restrict__ batch) {
    int g = blockIdx.x;
    int t = threadIdx.x;   // 128
    __shared__ int slo, shi;
    if (t == 0) {
        int lo = 0, hi = kN;
        while (lo < hi) { int mid = (lo + hi) >> 1; if (batch[mid] < g) lo = mid + 1; else hi = mid; }
        slo = lo;
        hi = kN;
        while (lo < hi) { int mid = (lo + hi) >> 1; if (batch[mid] < g + 1) lo = mid + 1; else hi = mid; }
        shi = lo;
    }
    __syncthreads();
    int lo = slo, hi = shi;
    float s = 0.f;
    for (int n = lo; n < hi; n++) s += g_x[n * kD + t];
    g_gsum[g * kD + t] = s / fmaxf((float)(hi - lo), 1.f);
}

__global__ void head(const float* __restrict__ hW, const float* __restrict__ hb,
                     float* __restrict__ out) {
    int g = blockIdx.x;
    int lane = threadIdx.x;
    float acc[kNC] = {};
    for (int k = lane; k < kD; k += 32) {
        float mm = g_gsum[g * kD + k];
#pragma unroll
        for (int c = 0; c < kNC; c++) acc[c] += mm * hW[k * kNC + c];
    }
#pragma unroll
    for (int c = 0; c < kNC; c++) {
        float v = acc[c];
#pragma unroll
        for (int o = 16; o > 0; o >>= 1) v += __shfl_down_sync(0xffffffffu, v, o);
        if (lane == 0) out[g * kNC + c] = v + hb[c];
    }
}

// ---------------- launch -----------------------------------------------------
extern "C" void kernel_launch(void* const* d_in, const int* in_sizes, int n_in,
                              void* d_out, int out_size) {
    const int*   x_nodes = (const int*)d_in[0];
    const int*   esrc    = (const int*)d_in[1];
    const int*   edst    = (const int*)d_in[2];
    const float* eattr   = (const float*)d_in[3];
    const int*   batch   = (const int*)d_in[4];
    const float* nemb    = (const float*)d_in[5];
    const float* edge_W  = (const float*)d_in[6];
    const float* edge_b  = (const float*)d_in[7];
    const float* Wl      = (const float*)d_in[8];
    const float* bl      = (const float*)d_in[9];
    const float* Wr      = (const float*)d_in[10];
    const float* br      = (const float*)d_in[11];
    const float* We      = (const float*)d_in[12];
    const float* att     = (const float*)d_in[13];
    const float* gbias   = (const float*)d_in[14];
    const float* bng     = (const float*)d_in[15];
    const float* bnb     = (const float*)d_in[16];
    const float* headW   = (const float*)d_in[17];
    const float* headb   = (const float*)d_in[18];
    float* out = (float*)d_out;

    init_enc<<<4096, 256>>>(x_nodes, nemb);                        // 1
    count_deg<<<(kE + 255) / 256, 256>>>(esrc, edst);              // 2
    scan1<<<kSB, 1024>>>();                                        // 3
    xlr_gemm<<<dim3((kN + 63) / 64, 2), 256>>>(Wl, bl, Wr, br, 0); // 4 (profiled)
    scan2<<<1, 32>>>();                                            // 5
    scan3<<<(kN + 255) / 256, 256>>>();                            // 6
    scatter_csr<<<(kE + 255) / 256, 256>>>(esrc, edst, eattr);     // 7
    int nbl = (kN * 8 + 1023) / 1024;
    prep<<<nbl + kL, 1024>>>(edge_W, edge_b, We);                  // 8
    fused_gat<<<(kN * 32 + 127) / 128, 128>>>(att, gbias, bng, bnb, 0);

    for (int i = 1; i < kL; i++) {
        xlr_gemm<<<dim3((kN + 63) / 64, 2), 256>>>(Wl, bl, Wr, br, i);
        fused_gat<<<(kN * 32 + 127) / 128, 128>>>(att, gbias, bng, bnb, i);
    }

    pool<<<kG, kD>>>(batch);
    head<<<kG, 32>>>(headW, headb, out);
}

// round 6
// speedup vs baseline: 1.2722x; 1.0047x over previous
#include <cuda_runtime.h>
#include <math.h>

constexpr int kN   = 50000;
constexpr int kE   = 800000;
constexpr int kG   = 512;
constexpr int kD   = 128;
constexpr int kEE  = 64;
constexpr int kL   = 4;
constexpr int kNC  = 10;
constexpr int kSB  = (kN + 1023) / 1024;
constexpr float kBNS = 0.9999950000374997f;  // (1+1e-5)^-0.5

typedef unsigned long long u64;

// ---------------- f32x2 packed helpers -------------------------------------
__device__ __forceinline__ u64 pack2(float lo, float hi) {
    u64 r; asm("mov.b64 %0,{%1,%2};" : "=l"(r) : "f"(lo), "f"(hi)); return r;
}
__device__ __forceinline__ u64 splat2(float v) { return pack2(v, v); }
__device__ __forceinline__ void unpack2(u64 p, float& lo, float& hi) {
    asm("mov.b64 {%0,%1},%2;" : "=f"(lo), "=f"(hi) : "l"(p));
}
__device__ __forceinline__ u64 fma2(u64 a, u64 b, u64 c) {
    u64 r; asm("fma.rn.f32x2 %0,%1,%2,%3;" : "=l"(r) : "l"(a), "l"(b), "l"(c)); return r;
}
__device__ __forceinline__ u64 add2(u64 a, u64 b) {
    u64 r; asm("add.rn.f32x2 %0,%1,%2;" : "=l"(r) : "l"(a), "l"(b)); return r;
}

// ---------------- scratch ----------------------------------------------------
__device__ float g_x[kN * kD];
__device__ float g_xl[kN * kD];
__device__ float g_xr[kN * kD];
__device__ float g_lraw[kN * 8];
__device__ int   g_deg[kN];
__device__ int   g_cur[kN];
__device__ int   g_scan[kN];
__device__ int   g_bt[kSB];
__device__ int   g_boff[kSB];
__device__ int   g_off[kN + 1];
__device__ int   g_csrc[kE];
__device__ float g_eraw[(size_t)kE * 8];
__device__ float g_M[kL * 8 * kD];
__device__ float g_bep[kL * kD];
__device__ float g_gsum[kG * kD];

// ---------------- 1: init + node encode --------------------------------------
__global__ void init_enc(const int* __restrict__ xn, const float* __restrict__ emb) {
    int i = blockIdx.x * blockDim.x + threadIdx.x;
    int stride = gridDim.x * blockDim.x;
    for (int t = i; t < kN; t += stride) { g_deg[t] = 0; g_cur[t] = 0; }
    for (int t = i; t < kN * kD; t += stride) {
        int n = t >> 7, j = t & 127;
        g_x[t] = emb[xn[n] * kD + j];
    }
}

// ---------------- 2: degree count --------------------------------------------
__global__ void count_deg(const int* __restrict__ src, const int* __restrict__ dst) {
    int e = blockIdx.x * blockDim.x + threadIdx.x;
    if (e >= kE) return;
    int s = src[e], d = dst[e];
    if (s != d) atomicAdd(&g_deg[d], 1);
}

// ---------------- scan -------------------------------------------------------
__global__ void scan1() {
    __shared__ int sh[1024];
    int n = blockIdx.x * 1024 + threadIdx.x;
    int v = (n < kN) ? g_deg[n] : 0;
    sh[threadIdx.x] = v;
    __syncthreads();
    for (int o = 1; o < 1024; o <<= 1) {
        int add = (threadIdx.x >= o) ? sh[threadIdx.x - o] : 0;
        __syncthreads();
        sh[threadIdx.x] += add;
        __syncthreads();
    }
    if (n < kN) g_scan[n] = sh[threadIdx.x];
    if (threadIdx.x == 1023) g_bt[blockIdx.x] = sh[1023];
}
__global__ void scan2() {
    if (threadIdx.x == 0) {
        int run = 0;
        for (int b = 0; b < kSB; b++) { g_boff[b] = run; run += g_bt[b]; }
        g_off[kN] = run;
    }
}
__global__ void scan3() {
    int n = blockIdx.x * blockDim.x + threadIdx.x;
    if (n < kN) g_off[n] = g_scan[n] - g_deg[n] + g_boff[n >> 10];
}

// ---------------- 4 (PROFILED): xl/xr GEMM -----------------------------------
__global__ __launch_bounds__(256) void xlr_gemm(
        const float* __restrict__ Wl, const float* __restrict__ bl,
        const float* __restrict__ Wr, const float* __restrict__ br, int layer) {
    const float* W = (blockIdx.y == 0 ? Wl : Wr) + layer * kD * kD;
    const float* bias = (blockIdx.y == 0 ? bl : br) + layer * kD;
    float* out = blockIdx.y == 0 ? g_xl : g_xr;

    __shared__ __align__(16) float ws[32 * 128];
    __shared__ __align__(16) float xs[32][68];

    int t = threadIdx.x;
    int lane = t & 31;
    int w = t >> 5;
    int n0 = blockIdx.x * 64;

    u64 acc[8][2] = {};
    for (int kt = 0; kt < kD; kt += 32) {
#pragma unroll
        for (int r = t; r < 32 * 128; r += 256)
            ws[r] = W[(kt + (r >> 7)) * kD + (r & 127)];
#pragma unroll
        for (int r = t; r < 64 * 32; r += 256) {
            int n = r >> 5, kk = r & 31;
            int nn = n0 + n;
            xs[kk][n] = (nn < kN) ? g_x[nn * kD + kt + kk] : 0.f;
        }
        __syncthreads();
#pragma unroll
        for (int kk = 0; kk < 32; kk++) {
            ulonglong2 wv = *(const ulonglong2*)&ws[kk * 128 + lane * 4];
            float4 xv0 = *(const float4*)&xs[kk][w * 8];
            float4 xv1 = *(const float4*)&xs[kk][w * 8 + 4];
            float xm[8] = {xv0.x, xv0.y, xv0.z, xv0.w, xv1.x, xv1.y, xv1.z, xv1.w};
#pragma unroll
            for (int m = 0; m < 8; m++) {
                u64 xp = splat2(xm[m]);
                acc[m][0] = fma2(xp, wv.x, acc[m][0]);
                acc[m][1] = fma2(xp, wv.y, acc[m][1]);
            }
        }
        __syncthreads();
    }
    float4 bv = *(const float4*)(bias + lane * 4);
#pragma unroll
    for (int m = 0; m < 8; m++) {
        int n = n0 + w * 8 + m;
        if (n < kN) {
            float a0, a1, a2, a3;
            unpack2(acc[m][0], a0, a1);
            unpack2(acc[m][1], a2, a3);
            float4 o = make_float4(a0 + bv.x, a1 + bv.y, a2 + bv.z, a3 + bv.w);
            *(float4*)&out[n * kD + lane * 4] = o;
        }
    }
}

// ---------------- scatter CSR + permute raw edge attrs ----------------------
__global__ void scatter_csr(const int* __restrict__ src, const int* __restrict__ dst,
                            const float* __restrict__ eattr) {
    int e = blockIdx.x * blockDim.x + threadIdx.x;
    if (e >= kE) return;
    int s = src[e], d = dst[e];
    if (s == d) return;
    int pos = atomicAdd(&g_cur[d], 1);
    int idx = g_off[d] + pos;
    g_csrc[idx] = s;
    float4 a = *(const float4*)&eattr[(size_t)e * 8];
    float4 b = *(const float4*)&eattr[(size_t)e * 8 + 4];
    *(float4*)&g_eraw[(size_t)idx * 8] = a;
    *(float4*)&g_eraw[(size_t)idx * 8 + 4] = b;
}

// ---------------- lraw + M/bep for all layers -------------------------------
__global__ void prep(const float* __restrict__ eW, const float* __restrict__ eb,
                     const float* __restrict__ We) {
    int nbl = (kN * 8 + 1023) / 1024;
    if ((int)blockIdx.x < nbl) {
        int t = blockIdx.x * 1024 + threadIdx.x;
        int n = t >> 3, j = t & 7;
        if (n >= kN) return;
        int beg = g_off[n], end = g_off[n + 1];
        float s = 0.f;
        for (int idx = beg; idx < end; idx++) s += g_eraw[(size_t)idx * 8 + j];
        int c = end - beg;
        g_lraw[n * 8 + j] = s / (float)(c > 1 ? c : 1);
    } else {
        int layer = blockIdx.x - nbl;
        int t = threadIdx.x;
        int k = t >> 7, j = t & 127;
        const float* w = We + (size_t)layer * kEE * kD;
        float acc = 0.f;
#pragma unroll 8
        for (int u = 0; u < kEE; u++) acc += eW[k * kEE + u] * w[u * kD + j];
        g_M[layer * 8 * kD + k * kD + j] = acc;
        if (t < kD) {
            float b = 0.f;
#pragma unroll 8
            for (int u = 0; u < kEE; u++) b += eb[u] * w[u * kD + t];
            g_bep[layer * kD + t] = b;
        }
    }
}

// ---------------- fused GAT layer: fixed-shift softmax (no serial chain) ----
__global__ __launch_bounds__(128) void fused_gat(
        const float* __restrict__ att, const float* __restrict__ gbias,
        const float* __restrict__ gam, const float* __restrict__ bet, int layer) {
    int t = threadIdx.x, lane = t & 31;
    int d = (blockIdx.x * 128 + t) >> 5;
    if (d >= kN) return;
    int j0 = lane * 4;

    u64 Mr[8][2];
#pragma unroll
    for (int k = 0; k < 8; k++) {
        float4 mv = *(const float4*)&g_M[layer * 8 * kD + k * kD + j0];
        Mr[k][0] = pack2(mv.x, mv.y);
        Mr[k][1] = pack2(mv.z, mv.w);
    }
    float4 attv = *(const float4*)&att[layer * kD + j0];
    float4 bep4 = *(const float4*)&g_bep[layer * kD + j0];
    float4 xld4 = *(const float4*)&g_xl[d * kD + j0];
    u64 xld0 = pack2(xld4.x, xld4.y), xld1 = pack2(xld4.z, xld4.w);

    int beg = g_off[d], end = g_off[d + 1];

    float4 gb = *(const float4*)&gbias[layer * kD + j0];
    float4 gm = *(const float4*)&gam[layer * kD + j0];
    float4 bt = *(const float4*)&bet[layer * kD + j0];

    float a0, a1, a2, a3;
    if (beg == end) {
        // single self loop -> alpha = 1
        a0 = xld4.x; a1 = xld4.y; a2 = xld4.z; a3 = xld4.w;
    } else {
        float4 xr4 = *(const float4*)&g_xr[d * kD + j0];
        u64 xrb0 = pack2(xr4.x + bep4.x, xr4.y + bep4.y);
        u64 xrb1 = pack2(xr4.z + bep4.z, xr4.w + bep4.w);

        // ---- self-loop logit = fixed softmax shift ----
        float4 lr1 = *(const float4*)&g_lraw[d * 8];
        float4 lr2 = *(const float4*)&g_lraw[d * 8 + 4];
        u64 e0 = add2(xrb0, xld0), e1 = add2(xrb1, xld1);
        {
            float rk[8] = {lr1.x, lr1.y, lr1.z, lr1.w, lr2.x, lr2.y, lr2.z, lr2.w};
#pragma unroll
            for (int k = 0; k < 8; k++) {
                u64 rp = splat2(rk[k]);
                e0 = fma2(rp, Mr[k][0], e0);
                e1 = fma2(rp, Mr[k][1], e1);
            }
        }
        float vx, vy, vz, vw;
        unpack2(e0, vx, vy); unpack2(e1, vz, vw);
        vx = fmaxf(vx, 0.2f * vx); vy = fmaxf(vy, 0.2f * vy);
        vz = fmaxf(vz, 0.2f * vz); vw = fmaxf(vw, 0.2f * vw);
        float lself = vx * attv.x + vy * attv.y + vz * attv.z + vw * attv.w;
        lself += __shfl_xor_sync(0xffffffffu, lself, 1);
        lself += __shfl_xor_sync(0xffffffffu, lself, 2);

        float den = 1.f;               // self loop: exp(lself - lself) = 1
        u64 acc0 = xld0, acc1 = xld1;

        // ---- feed-forward edge loop, depth-2 prefetch ----
        int i = beg;
        int sN = g_csrc[i];
        float4 raN = *(const float4*)&g_eraw[(size_t)i * 8];
        float4 rbN = *(const float4*)&g_eraw[(size_t)i * 8 + 4];
        float4 xlN = *(const float4*)&g_xl[sN * kD + j0];
        int sNN = 0; float4 raNN = {}, rbNN = {};
        if (i + 1 < end) {
            sNN = g_csrc[i + 1];
            raNN = *(const float4*)&g_eraw[(size_t)(i + 1) * 8];
            rbNN = *(const float4*)&g_eraw[(size_t)(i + 1) * 8 + 4];
        }
        for (; i < end; i++) {
            float4 xls = xlN, ra = raN, rb = rbN;
            if (i + 1 < end) {
                xlN = *(const float4*)&g_xl[sNN * kD + j0];
                raN = raNN; rbN = rbNN;
            }
            if (i + 2 < end) {
                sNN = g_csrc[i + 2];
                raNN = *(const float4*)&g_eraw[(size_t)(i + 2) * 8];
                rbNN = *(const float4*)&g_eraw[(size_t)(i + 2) * 8 + 4];
            }
            u64 xlsp0 = pack2(xls.x, xls.y), xlsp1 = pack2(xls.z, xls.w);
            u64 f0 = add2(xrb0, xlsp0), f1 = add2(xrb1, xlsp1);
            float rk[8] = {ra.x, ra.y, ra.z, ra.w, rb.x, rb.y, rb.z, rb.w};
#pragma unroll
            for (int k = 0; k < 8; k++) {
                u64 rp = splat2(rk[k]);
                f0 = fma2(rp, Mr[k][0], f0);
                f1 = fma2(rp, Mr[k][1], f1);
            }
            float ax, ay, az, aw;
            unpack2(f0, ax, ay); unpack2(f1, az, aw);
            ax = fmaxf(ax, 0.2f * ax); ay = fmaxf(ay, 0.2f * ay);
            az = fmaxf(az, 0.2f * az); aw = fmaxf(aw, 0.2f * aw);
            float l2 = ax * attv.x + ay * attv.y + az * attv.z + aw * attv.w;
            l2 += __shfl_xor_sync(0xffffffffu, l2, 1);
            l2 += __shfl_xor_sync(0xffffffffu, l2, 2);

            float p = __expf(l2 - lself);
            den += p;
            u64 pp = splat2(p);
            acc0 = fma2(pp, xlsp0, acc0);
            acc1 = fma2(pp, xlsp1, acc1);
        }
        float inv = 1.f / den;
        float c0, c1, c2, c3;
        unpack2(acc0, c0, c1); unpack2(acc1, c2, c3);
        a0 = c0 * inv; a1 = c1 * inv; a2 = c2 * inv; a3 = c3 * inv;
    }

    float w0 = gm.x * (a0 + gb.x) * kBNS + bt.x;
    float w1 = gm.y * (a1 + gb.y) * kBNS + bt.y;
    float w2 = gm.z * (a2 + gb.z) * kBNS + bt.z;
    float w3 = gm.w * (a3 + gb.w) * kBNS + bt.w;
    float4 o;
    o.x = w0 > 0.f ? w0 : expm1f(w0);
    o.y = w1 > 0.f ? w1 : expm1f(w1);
    o.z = w2 > 0.f ? w2 : expm1f(w2);
    o.w = w3 > 0.f ? w3 : expm1f(w3);
    *(float4*)&g_x[d * kD + j0] = o;
}

// ---------------- pool + head ------------------------------------------------
__global__ void pool(const int* __restrict__ batch) {
    int g = blockIdx.x;
    int t = threadIdx.x;   // 128
    __shared__ int slo, shi;
    if (t == 0) {
        int lo = 0, hi = kN;
        while (lo < hi) { int mid = (lo + hi) >> 1; if (batch[mid] < g) lo = mid + 1; else hi = mid; }
        slo = lo;
        hi = kN;
        while (lo < hi) { int mid = (lo + hi) >> 1; if (batch[mid] < g + 1) lo = mid + 1; else hi = mid; }
        shi = lo;
    }
    __syncthreads();
    int lo = slo, hi = shi;
    float s = 0.f;
    for (int n = lo; n < hi; n++) s += g_x[n * kD + t];
    g_gsum[g * kD + t] = s / fmaxf((float)(hi - lo), 1.f);
}

__global__ void head(const float* __restrict__ hW, const float* __restrict__ hb,
                     float* __restrict__ out) {
    int g = blockIdx.x;
    int lane = threadIdx.x;
    float acc[kNC] = {};
    for (int k = lane; k < kD; k += 32) {
        float mm = g_gsum[g * kD + k];
#pragma unroll
        for (int c = 0; c < kNC; c++) acc[c] += mm * hW[k * kNC + c];
    }
#pragma unroll
    for (int c = 0; c < kNC; c++) {
        float v = acc[c];
#pragma unroll
        for (int o = 16; o > 0; o >>= 1) v += __shfl_down_sync(0xffffffffu, v, o);
        if (lane == 0) out[g * kNC + c] = v + hb[c];
    }
}

// ---------------- launch -----------------------------------------------------
extern "C" void kernel_launch(void* const* d_in, const int* in_sizes, int n_in,
                              void* d_out, int out_size) {
    const int*   x_nodes = (const int*)d_in[0];
    const int*   esrc    = (const int*)d_in[1];
    const int*   edst    = (const int*)d_in[2];
    const float* eattr   = (const float*)d_in[3];
    const int*   batch   = (const int*)d_in[4];
    const float* nemb    = (const float*)d_in[5];
    const float* edge_W  = (const float*)d_in[6];
    const float* edge_b  = (const float*)d_in[7];
    const float* Wl      = (const float*)d_in[8];
    const float* bl      = (const float*)d_in[9];
    const float* Wr      = (const float*)d_in[10];
    const float* br      = (const float*)d_in[11];
    const float* We      = (const float*)d_in[12];
    const float* att     = (const float*)d_in[13];
    const float* gbias   = (const float*)d_in[14];
    const float* bng     = (const float*)d_in[15];
    const float* bnb     = (const float*)d_in[16];
    const float* headW   = (const float*)d_in[17];
    const float* headb   = (const float*)d_in[18];
    float* out = (float*)d_out;

    init_enc<<<4096, 256>>>(x_nodes, nemb);                        // 1
    count_deg<<<(kE + 255) / 256, 256>>>(esrc, edst);              // 2
    scan1<<<kSB, 1024>>>();                                        // 3
    xlr_gemm<<<dim3((kN + 63) / 64, 2), 256>>>(Wl, bl, Wr, br, 0); // 4 (profiled)
    scan2<<<1, 32>>>();                                            // 5
    scan3<<<(kN + 255) / 256, 256>>>();                            // 6
    scatter_csr<<<(kE + 255) / 256, 256>>>(esrc, edst, eattr);     // 7
    int nbl = (kN * 8 + 1023) / 1024;
    prep<<<nbl + kL, 1024>>>(edge_W, edge_b, We);                  // 8
    fused_gat<<<(kN * 32 + 127) / 128, 128>>>(att, gbias, bng, bnb, 0);

    for (int i = 1; i < kL; i++) {
        xlr_gemm<<<dim3((kN + 63) / 64, 2), 256>>>(Wl, bl, Wr, br, i);
        fused_gat<<<(kN * 32 + 127) / 128, 128>>>(att, gbias, bng, bnb, i);
    }

    pool<<<kG, kD>>>(batch);
    head<<<kG, 32>>>(headW, headb, out);
}